// round 1
// baseline (speedup 1.0000x reference)
#include <cuda_runtime.h>

typedef unsigned long long ULL;

__device__ __forceinline__ ULL fma2(ULL a, ULL b, ULL c) {
    ULL d;
    asm("fma.rn.f32x2 %0, %1, %2, %3;" : "=l"(d) : "l"(a), "l"(b), "l"(c));
    return d;
}
__device__ __forceinline__ ULL pack2(float x, float y) {
    ULL r;
    asm("mov.b64 %0, {%1, %2};" : "=l"(r) : "r"(__float_as_uint(x)), "r"(__float_as_uint(y)));
    return r;
}
__device__ __forceinline__ float2 unpack2(ULL v) {
    unsigned lo, hi;
    asm("mov.b64 {%0, %1}, %2;" : "=r"(lo), "=r"(hi) : "l"(v));
    return make_float2(__uint_as_float(lo), __uint_as_float(hi));
}

// Scratch (allocation rules forbid cudaMalloc; __device__ globals are allowed)
__device__ float g_s [1024 * 256];
__device__ float g_t [1024 * 256];
__device__ float g_s2[1024 * 256];
__device__ float g_t2[1024 * 256];

// ---------------------------------------------------------------------------
// gemm64: C[m][n] = act( sum_k A[m*K+k] * B[n*ldb+k] + bias[n] )
// 64x64 CTA tile, 256 threads, 4m x 4n per thread, packed f32x2 FMA.
// blockIdx.z selects the {A,B,bias,C} set (runs s-branch and t-branch
// concurrently to fill the chip).
// ---------------------------------------------------------------------------
__global__ __launch_bounds__(256) void gemm64(
    const float* __restrict__ A0, const float* __restrict__ A1,
    const float* __restrict__ B0, const float* __restrict__ B1,
    const float* __restrict__ bias0, const float* __restrict__ bias1,
    float* __restrict__ C0, float* __restrict__ C1,
    int K, int ldb, int N, int relu)
{
    const float* A    = blockIdx.z ? A1 : A0;
    const float* B    = blockIdx.z ? B1 : B0;
    const float* bias = blockIdx.z ? bias1 : bias0;
    float*       C    = blockIdx.z ? C1 : C0;

    const int m0 = blockIdx.y * 64;
    const int n0 = blockIdx.x * 64;

    __shared__ __align__(16) float As[32][68];
    __shared__ __align__(16) float Bs[32][68];

    const int tid = threadIdx.x;
    const int tm  = tid >> 4;   // 0..15
    const int tn  = tid & 15;   // 0..15

    ULL acc[4][2];
#pragma unroll
    for (int i = 0; i < 4; i++) { acc[i][0] = 0ull; acc[i][1] = 0ull; }

    for (int k0 = 0; k0 < K; k0 += 32) {
#pragma unroll
        for (int r = 0; r < 2; r++) {
            int q   = tid + r * 256;      // 0..511
            int row = q >> 3;             // 0..63
            int c   = (q & 7) * 4;        // 0..28
            float4 va = *(const float4*)(A + (size_t)(m0 + row) * K + k0 + c);
            As[c    ][row] = va.x;
            As[c + 1][row] = va.y;
            As[c + 2][row] = va.z;
            As[c + 3][row] = va.w;
            float4 vb = *(const float4*)(B + (size_t)(n0 + row) * ldb + k0 + c);
            Bs[c    ][row] = vb.x;
            Bs[c + 1][row] = vb.y;
            Bs[c + 2][row] = vb.z;
            Bs[c + 3][row] = vb.w;
        }
        __syncthreads();

#pragma unroll 8
        for (int k = 0; k < 32; k++) {
            float4     av = *(const float4*)    &As[k][tm * 4];
            ulonglong2 bv = *(const ulonglong2*)&Bs[k][tn * 4];
            ULL a0 = pack2(av.x, av.x);
            ULL a1 = pack2(av.y, av.y);
            ULL a2 = pack2(av.z, av.z);
            ULL a3 = pack2(av.w, av.w);
            acc[0][0] = fma2(a0, bv.x, acc[0][0]);
            acc[0][1] = fma2(a0, bv.y, acc[0][1]);
            acc[1][0] = fma2(a1, bv.x, acc[1][0]);
            acc[1][1] = fma2(a1, bv.y, acc[1][1]);
            acc[2][0] = fma2(a2, bv.x, acc[2][0]);
            acc[2][1] = fma2(a2, bv.y, acc[2][1]);
            acc[3][0] = fma2(a3, bv.x, acc[3][0]);
            acc[3][1] = fma2(a3, bv.y, acc[3][1]);
        }
        __syncthreads();
    }

    float b0 = 0.f, b1 = 0.f, b2 = 0.f, b3 = 0.f;
    if (bias) {
        b0 = bias[n0 + tn * 4];
        b1 = bias[n0 + tn * 4 + 1];
        b2 = bias[n0 + tn * 4 + 2];
        b3 = bias[n0 + tn * 4 + 3];
    }
#pragma unroll
    for (int i = 0; i < 4; i++) {
        float2 c01 = unpack2(acc[i][0]);
        float2 c23 = unpack2(acc[i][1]);
        float4 o = make_float4(c01.x + b0, c01.y + b1, c23.x + b2, c23.y + b3);
        if (relu) {
            o.x = fmaxf(o.x, 0.f); o.y = fmaxf(o.y, 0.f);
            o.z = fmaxf(o.z, 0.f); o.w = fmaxf(o.w, 0.f);
        }
        *(float4*)(C + (size_t)(m0 + tm * 4 + i) * N + n0 + tn * 4) = o;
    }
}

// ---------------------------------------------------------------------------
// pair_kernel: out[b,i,n,j] = sum_h relu(s2[b,i,h] + t2[b,j,h]) * fc3[n,h]
// CTA: 8 i x 64 j, 128 threads. Thread: 2 i x 2 j (j-pair packed in f32x2),
// 25 n accumulators per i => 50 u64 accumulator regs.
// fc3 stored in smem as {w,w} duplicated float2 so a single LDS.128 broadcast
// delivers the packed multipliers for two n's -> 4 FFMA2 per 1 LDS.
// ---------------------------------------------------------------------------
#define TI 8
#define TJ 64
#define HC 64

__global__ __launch_bounds__(128, 3) void pair_kernel(
    const float* __restrict__ s2, const float* __restrict__ t2,
    const float* __restrict__ fc3, float* __restrict__ out)
{
    const int b  = blockIdx.z;   // 0..3
    const int it = blockIdx.y;   // 0..31
    const int jt = blockIdx.x;   // 0..3

    __shared__ __align__(16) float  s_sm[HC][TI + 2];
    __shared__ __align__(16) float  t_sm[HC][TJ + 2];
    __shared__ __align__(16) float2 w_sm[HC][26];

    const int tid  = threadIdx.x;
    const int warp = tid >> 5;    // 0..3
    const int lane = tid & 31;
    const int i0   = warp * 2;    // local i pair

    const float* s2g = s2 + (size_t)(b * 256 + it * TI) * 256;
    const float* t2g = t2 + (size_t)(b * 256 + jt * TJ) * 256;

    ULL accA[25], accB[25];
#pragma unroll
    for (int n = 0; n < 25; n++) { accA[n] = 0ull; accB[n] = 0ull; }

    for (int hc = 0; hc < 256 / HC; hc++) {
        const int h0 = hc * HC;

        // s tile: 8 rows x 64 h = 128 float4, one per thread
        {
            int m = tid >> 4;          // 0..7
            int c = (tid & 15) * 4;    // 0..60
            float4 v = *(const float4*)(s2g + m * 256 + h0 + c);
            s_sm[c    ][m] = v.x;
            s_sm[c + 1][m] = v.y;
            s_sm[c + 2][m] = v.z;
            s_sm[c + 3][m] = v.w;
        }
        // t tile: 64 rows x 64 h = 1024 float4, 8 per thread
#pragma unroll
        for (int r = 0; r < 8; r++) {
            int q   = tid + r * 128;
            int row = q >> 4;          // 0..63
            int c   = (q & 15) * 4;
            float4 v = *(const float4*)(t2g + row * 256 + h0 + c);
            t_sm[c    ][row] = v.x;
            t_sm[c + 1][row] = v.y;
            t_sm[c + 2][row] = v.z;
            t_sm[c + 3][row] = v.w;
        }
        // fc3 tile: 25 n x 64 h, stored duplicated {w,w}
        for (int q = tid; q < 25 * HC; q += 128) {
            int n = q >> 6;
            int h = q & 63;
            float v = fc3[n * 256 + h0 + h];
            w_sm[h][n] = make_float2(v, v);
        }
        __syncthreads();

#pragma unroll 2
        for (int h = 0; h < HC; h++) {
            float  sa = s_sm[h][i0];
            float  sb = s_sm[h][i0 + 1];
            float2 tv = *(const float2*)&t_sm[h][lane * 2];
            ULL PA = pack2(fmaxf(sa + tv.x, 0.f), fmaxf(sa + tv.y, 0.f));
            ULL PB = pack2(fmaxf(sb + tv.x, 0.f), fmaxf(sb + tv.y, 0.f));
#pragma unroll
            for (int np = 0; np < 12; np++) {
                ulonglong2 w = *(const ulonglong2*)&w_sm[h][2 * np];
                accA[2 * np    ] = fma2(PA, w.x, accA[2 * np    ]);
                accA[2 * np + 1] = fma2(PA, w.y, accA[2 * np + 1]);
                accB[2 * np    ] = fma2(PB, w.x, accB[2 * np    ]);
                accB[2 * np + 1] = fma2(PB, w.y, accB[2 * np + 1]);
            }
            ULL wt = *(const ULL*)&w_sm[h][24];
            accA[24] = fma2(PA, wt, accA[24]);
            accB[24] = fma2(PB, wt, accB[24]);
        }
        __syncthreads();
    }

    // out[b][i][n][j], j-pair contiguous -> STG.64, fully coalesced per warp
    const int gi0 = it * TI + i0;
    const int j0  = jt * TJ + lane * 2;
    float* o0 = out + (size_t)(b * 256 + gi0)     * 25 * 256 + j0;
    float* o1 = out + (size_t)(b * 256 + gi0 + 1) * 25 * 256 + j0;
#pragma unroll
    for (int n = 0; n < 25; n++) {
        *(float2*)(o0 + n * 256) = unpack2(accA[n]);
        *(float2*)(o1 + n * 256) = unpack2(accB[n]);
    }
}

// ---------------------------------------------------------------------------
// Inputs (metadata order):
// 0 input_tensor [4,256,768]  1 s_fc_w [256,768]  2 s_fc_b [256]
// 3 t_fc_w [256,768]          4 t_fc_b [256]      5 fc2_w [256,512]
// 6 fc2_b [256]               7 fc3_w [25,256]
// Output: float32 [4,256,25,256]
// ---------------------------------------------------------------------------
extern "C" void kernel_launch(void* const* d_in, const int* in_sizes, int n_in,
                              void* d_out, int out_size)
{
    const float* X  = (const float*)d_in[0];
    const float* sw = (const float*)d_in[1];
    const float* sb = (const float*)d_in[2];
    const float* tw = (const float*)d_in[3];
    const float* tb = (const float*)d_in[4];
    const float* w2 = (const float*)d_in[5];
    const float* b2 = (const float*)d_in[6];
    const float* w3 = (const float*)d_in[7];
    float* out = (float*)d_out;

    float *gs, *gt, *gs2, *gt2;
    cudaGetSymbolAddress((void**)&gs,  g_s);
    cudaGetSymbolAddress((void**)&gt,  g_t);
    cudaGetSymbolAddress((void**)&gs2, g_s2);
    cudaGetSymbolAddress((void**)&gt2, g_t2);

    dim3 blk(256);
    dim3 g1(256 / 64, 1024 / 64, 2);
    // s = relu(X @ s_fc_w^T + s_fc_b), t = relu(X @ t_fc_w^T + t_fc_b)
    gemm64<<<g1, blk>>>(X, X, sw, tw, sb, tb, gs, gt, 768, 768, 256, 1);
    // s2 = s @ w_s^T ; t2 = t @ w_t^T + fc2_b   (w_s = fc2_w[:, :256], w_t = fc2_w[:, 256:])
    gemm64<<<g1, blk>>>(gs, gt, w2, w2 + 256, nullptr, b2, gs2, gt2, 256, 512, 256, 0);

    dim3 g3(256 / TJ, 256 / TI, 4);
    pair_kernel<<<g3, dim3(128)>>>(gs2, gt2, w3, out);
}

// round 2
// speedup vs baseline: 1.0336x; 1.0336x over previous
#include <cuda_runtime.h>

typedef unsigned long long ULL;

__device__ __forceinline__ ULL fma2(ULL a, ULL b, ULL c) {
    ULL d;
    asm("fma.rn.f32x2 %0, %1, %2, %3;" : "=l"(d) : "l"(a), "l"(b), "l"(c));
    return d;
}
__device__ __forceinline__ ULL pack2(float x, float y) {
    ULL r;
    asm("mov.b64 %0, {%1, %2};" : "=l"(r) : "r"(__float_as_uint(x)), "r"(__float_as_uint(y)));
    return r;
}
__device__ __forceinline__ float2 unpack2(ULL v) {
    unsigned lo, hi;
    asm("mov.b64 {%0, %1}, %2;" : "=r"(lo), "=r"(hi) : "l"(v));
    return make_float2(__uint_as_float(lo), __uint_as_float(hi));
}

// Scratch (allocation rules forbid cudaMalloc; __device__ globals are allowed)
__device__ float g_s [1024 * 256];
__device__ float g_t [1024 * 256];
__device__ float g_s2[1024 * 256];
__device__ float g_t2[1024 * 256];

// ---------------------------------------------------------------------------
// gemm32: C[m][n] = act( sum_k A[m*K+k] * B[n*ldb+k] + bias[n] )
// 32x32 CTA tile, 128 threads, thread = 4m x 2n, BK=16, double-buffered smem
// (one __syncthreads per K-chunk), register prefetch of next chunk overlaps
// LDG with compute. blockIdx.z selects the {A,B,bias,C} set so the s- and
// t-branches run concurrently. grid = 512 CTAs (3.5/SM) vs 128 before.
// ---------------------------------------------------------------------------
#define GBM 32
#define GBN 32
#define GBK 16

__global__ __launch_bounds__(128) void gemm32(
    const float* __restrict__ A0, const float* __restrict__ A1,
    const float* __restrict__ B0, const float* __restrict__ B1,
    const float* __restrict__ bias0, const float* __restrict__ bias1,
    float* __restrict__ C0, float* __restrict__ C1,
    int K, int ldb, int N, int relu)
{
    const float* A    = blockIdx.z ? A1 : A0;
    const float* B    = blockIdx.z ? B1 : B0;
    const float* bias = blockIdx.z ? bias1 : bias0;
    float*       C    = blockIdx.z ? C1 : C0;

    const int m0 = blockIdx.y * GBM;
    const int n0 = blockIdx.x * GBN;

    // [buf][k][row], padded
    __shared__ __align__(16) float As[2][GBK][GBM + 4];
    __shared__ __align__(16) float Bs[2][GBK][GBN + 4];

    const int tid = threadIdx.x;
    const int tm  = tid >> 4;        // 0..7  -> rows tm*4..tm*4+3
    const int tn  = tid & 15;        // 0..15 -> cols tn*2..tn*2+1

    // loader coords: 4 consecutive k per thread
    const int lrow = tid >> 2;       // 0..31
    const int lc   = (tid & 3) * 4;  // 0,4,8,12

    const float* Aptr = A + (size_t)(m0 + lrow) * K   + lc;
    const float* Bptr = B + (size_t)(n0 + lrow) * ldb + lc;

    ULL acc[4];                      // 4m x 2n packed
#pragma unroll
    for (int i = 0; i < 4; i++) acc[i] = 0ull;

    const int KC = K / GBK;

    float4 pa = *(const float4*)(Aptr);
    float4 pb = *(const float4*)(Bptr);

    {   // stage chunk 0
        As[0][lc    ][lrow] = pa.x;
        As[0][lc + 1][lrow] = pa.y;
        As[0][lc + 2][lrow] = pa.z;
        As[0][lc + 3][lrow] = pa.w;
        Bs[0][lc    ][lrow] = pb.x;
        Bs[0][lc + 1][lrow] = pb.y;
        Bs[0][lc + 2][lrow] = pb.z;
        Bs[0][lc + 3][lrow] = pb.w;
    }
    __syncthreads();

    for (int kc = 0; kc < KC; kc++) {
        const int cur = kc & 1;
        if (kc + 1 < KC) {
            pa = *(const float4*)(Aptr + (kc + 1) * GBK);
            pb = *(const float4*)(Bptr + (kc + 1) * GBK);
        }
#pragma unroll
        for (int k = 0; k < GBK; k++) {
            float4 av = *(const float4*)&As[cur][k][tm * 4];
            ULL    bv = *(const ULL*)   &Bs[cur][k][tn * 2];
            acc[0] = fma2(pack2(av.x, av.x), bv, acc[0]);
            acc[1] = fma2(pack2(av.y, av.y), bv, acc[1]);
            acc[2] = fma2(pack2(av.z, av.z), bv, acc[2]);
            acc[3] = fma2(pack2(av.w, av.w), bv, acc[3]);
        }
        if (kc + 1 < KC) {
            const int nxt = cur ^ 1;
            As[nxt][lc    ][lrow] = pa.x;
            As[nxt][lc + 1][lrow] = pa.y;
            As[nxt][lc + 2][lrow] = pa.z;
            As[nxt][lc + 3][lrow] = pa.w;
            Bs[nxt][lc    ][lrow] = pb.x;
            Bs[nxt][lc + 1][lrow] = pb.y;
            Bs[nxt][lc + 2][lrow] = pb.z;
            Bs[nxt][lc + 3][lrow] = pb.w;
            __syncthreads();
        }
    }

    float b0 = 0.f, b1 = 0.f;
    if (bias) {
        b0 = bias[n0 + tn * 2];
        b1 = bias[n0 + tn * 2 + 1];
    }
#pragma unroll
    for (int i = 0; i < 4; i++) {
        float2 c = unpack2(acc[i]);
        c.x += b0; c.y += b1;
        if (relu) { c.x = fmaxf(c.x, 0.f); c.y = fmaxf(c.y, 0.f); }
        *(float2*)(C + (size_t)(m0 + tm * 4 + i) * N + n0 + tn * 2) = c;
    }
}

// ---------------------------------------------------------------------------
// pair_kernel: out[b,i,n,j] = sum_h relu(s2[b,i,h] + t2[b,j,h]) * fc3[n,h]
// CTA: 8 i x 64 j, 128 threads. Thread: 2 i x 2 j (j-pair packed in f32x2),
// 25 n accumulators per i => 50 u64 accumulator regs.
// fc3 stored in smem as {w,w} duplicated float2 so a single LDS.128 broadcast
// delivers the packed multipliers for two n's -> 4 FFMA2 per 1 LDS.
// h-loop unrolled 4x so LDS latency pipelines behind FFMA2 chains.
// ---------------------------------------------------------------------------
#define TI 8
#define TJ 64
#define HC 64

__global__ __launch_bounds__(128, 3) void pair_kernel(
    const float* __restrict__ s2, const float* __restrict__ t2,
    const float* __restrict__ fc3, float* __restrict__ out)
{
    const int b  = blockIdx.z;   // 0..3
    const int it = blockIdx.y;   // 0..31
    const int jt = blockIdx.x;   // 0..3

    __shared__ __align__(16) float  s_sm[HC][TI + 2];
    __shared__ __align__(16) float  t_sm[HC][TJ + 2];
    __shared__ __align__(16) float2 w_sm[HC][26];

    const int tid  = threadIdx.x;
    const int warp = tid >> 5;    // 0..3
    const int lane = tid & 31;
    const int i0   = warp * 2;    // local i pair

    const float* s2g = s2 + (size_t)(b * 256 + it * TI) * 256;
    const float* t2g = t2 + (size_t)(b * 256 + jt * TJ) * 256;

    ULL accA[25], accB[25];
#pragma unroll
    for (int n = 0; n < 25; n++) { accA[n] = 0ull; accB[n] = 0ull; }

    for (int hc = 0; hc < 256 / HC; hc++) {
        const int h0 = hc * HC;

        // s tile: 8 rows x 64 h = 128 float4, one per thread
        {
            int m = tid >> 4;          // 0..7
            int c = (tid & 15) * 4;    // 0..60
            float4 v = *(const float4*)(s2g + m * 256 + h0 + c);
            s_sm[c    ][m] = v.x;
            s_sm[c + 1][m] = v.y;
            s_sm[c + 2][m] = v.z;
            s_sm[c + 3][m] = v.w;
        }
        // t tile: 64 rows x 64 h = 1024 float4, 8 per thread
#pragma unroll
        for (int r = 0; r < 8; r++) {
            int q   = tid + r * 128;
            int row = q >> 4;          // 0..63
            int c   = (q & 15) * 4;
            float4 v = *(const float4*)(t2g + row * 256 + h0 + c);
            t_sm[c    ][row] = v.x;
            t_sm[c + 1][row] = v.y;
            t_sm[c + 2][row] = v.z;
            t_sm[c + 3][row] = v.w;
        }
        // fc3 tile: 25 n x 64 h, stored duplicated {w,w}
        for (int q = tid; q < 25 * HC; q += 128) {
            int n = q >> 6;
            int h = q & 63;
            float v = fc3[n * 256 + h0 + h];
            w_sm[h][n] = make_float2(v, v);
        }
        __syncthreads();

#pragma unroll 4
        for (int h = 0; h < HC; h++) {
            float  sa = s_sm[h][i0];
            float  sb = s_sm[h][i0 + 1];
            float2 tv = *(const float2*)&t_sm[h][lane * 2];
            ULL PA = pack2(fmaxf(sa + tv.x, 0.f), fmaxf(sa + tv.y, 0.f));
            ULL PB = pack2(fmaxf(sb + tv.x, 0.f), fmaxf(sb + tv.y, 0.f));
#pragma unroll
            for (int np = 0; np < 12; np++) {
                ulonglong2 w = *(const ulonglong2*)&w_sm[h][2 * np];
                accA[2 * np    ] = fma2(PA, w.x, accA[2 * np    ]);
                accA[2 * np + 1] = fma2(PA, w.y, accA[2 * np + 1]);
                accB[2 * np    ] = fma2(PB, w.x, accB[2 * np    ]);
                accB[2 * np + 1] = fma2(PB, w.y, accB[2 * np + 1]);
            }
            ULL wt = *(const ULL*)&w_sm[h][24];
            accA[24] = fma2(PA, wt, accA[24]);
            accB[24] = fma2(PB, wt, accB[24]);
        }
        __syncthreads();
    }

    // out[b][i][n][j], j-pair contiguous -> STG.64, fully coalesced per warp
    const int gi0 = it * TI + i0;
    const int j0  = jt * TJ + lane * 2;
    float* o0 = out + (size_t)(b * 256 + gi0)     * 25 * 256 + j0;
    float* o1 = out + (size_t)(b * 256 + gi0 + 1) * 25 * 256 + j0;
#pragma unroll
    for (int n = 0; n < 25; n++) {
        *(float2*)(o0 + n * 256) = unpack2(accA[n]);
        *(float2*)(o1 + n * 256) = unpack2(accB[n]);
    }
}

// ---------------------------------------------------------------------------
// Inputs (metadata order):
// 0 input_tensor [4,256,768]  1 s_fc_w [256,768]  2 s_fc_b [256]
// 3 t_fc_w [256,768]          4 t_fc_b [256]      5 fc2_w [256,512]
// 6 fc2_b [256]               7 fc3_w [25,256]
// Output: float32 [4,256,25,256]
// ---------------------------------------------------------------------------
extern "C" void kernel_launch(void* const* d_in, const int* in_sizes, int n_in,
                              void* d_out, int out_size)
{
    const float* X  = (const float*)d_in[0];
    const float* sw = (const float*)d_in[1];
    const float* sb = (const float*)d_in[2];
    const float* tw = (const float*)d_in[3];
    const float* tb = (const float*)d_in[4];
    const float* w2 = (const float*)d_in[5];
    const float* b2 = (const float*)d_in[6];
    const float* w3 = (const float*)d_in[7];
    float* out = (float*)d_out;

    float *gs, *gt, *gs2, *gt2;
    cudaGetSymbolAddress((void**)&gs,  g_s);
    cudaGetSymbolAddress((void**)&gt,  g_t);
    cudaGetSymbolAddress((void**)&gs2, g_s2);
    cudaGetSymbolAddress((void**)&gt2, g_t2);

    dim3 blk(128);
    dim3 g1(256 / GBN, 1024 / GBM, 2);   // 8 x 32 x 2 = 512 CTAs
    // s = relu(X @ s_fc_w^T + s_fc_b), t = relu(X @ t_fc_w^T + t_fc_b)
    gemm32<<<g1, blk>>>(X, X, sw, tw, sb, tb, gs, gt, 768, 768, 256, 1);
    // s2 = s @ w_s^T ; t2 = t @ w_t^T + fc2_b   (w_s = fc2_w[:, :256], w_t = fc2_w[:, 256:])
    gemm32<<<g1, blk>>>(gs, gt, w2, w2 + 256, nullptr, b2, gs2, gt2, 256, 512, 256, 0);

    dim3 g3(256 / TJ, 256 / TI, 4);      // 4 x 32 x 4 = 512 CTAs
    pair_kernel<<<g3, dim3(128)>>>(gs2, gt2, w3, out);
}

// round 4
// speedup vs baseline: 1.3532x; 1.3092x over previous
#include <cuda_runtime.h>

typedef unsigned long long ULL;
typedef unsigned int U32;

__device__ __forceinline__ ULL fma2(ULL a, ULL b, ULL c) {
    ULL d;
    asm("fma.rn.f32x2 %0, %1, %2, %3;" : "=l"(d) : "l"(a), "l"(b), "l"(c));
    return d;
}
__device__ __forceinline__ ULL pack2(float x, float y) {
    ULL r;
    asm("mov.b64 %0, {%1, %2};" : "=l"(r) : "r"(__float_as_uint(x)), "r"(__float_as_uint(y)));
    return r;
}
__device__ __forceinline__ float2 unpack2(ULL v) {
    unsigned lo, hi;
    asm("mov.b64 {%0, %1}, %2;" : "=r"(lo), "=r"(hi) : "l"(v));
    return make_float2(__uint_as_float(lo), __uint_as_float(hi));
}
__device__ __forceinline__ U32 tf32r(float x) {
    U32 r;
    asm("cvt.rna.tf32.f32 %0, %1;" : "=r"(r) : "f"(x));
    return r;
}

// Scratch (cudaMalloc is forbidden; __device__ globals are allowed)
__device__ float g_s [1024 * 256];
__device__ float g_t [1024 * 256];
__device__ float g_s2[1024 * 256];
__device__ float g_t2[1024 * 256];

// ---------------------------------------------------------------------------
// gemm_s: C[m][n] = act( sum_k A[m*K+k] * B[n*ldb+k] + bias[n] )
// 32x32 CTA tile, 64 threads, thread = 4m x 4n, BK=16, double-buffered smem
// + register prefetch. blockIdx.z selects {A,B,bias,C} (s/t branches run
// concurrently).
// ---------------------------------------------------------------------------
#define GBK 16

__global__ __launch_bounds__(64) void gemm_s(
    const float* __restrict__ A0, const float* __restrict__ A1,
    const float* __restrict__ B0, const float* __restrict__ B1,
    const float* __restrict__ bias0, const float* __restrict__ bias1,
    float* __restrict__ C0, float* __restrict__ C1,
    int K, int ldb, int N, int relu)
{
    const float* A    = blockIdx.z ? A1 : A0;
    const float* B    = blockIdx.z ? B1 : B0;
    const float* bias = blockIdx.z ? bias1 : bias0;
    float*       C    = blockIdx.z ? C1 : C0;

    const int m0 = blockIdx.y * 32;
    const int n0 = blockIdx.x * 32;

    __shared__ __align__(16) float As[2][GBK][36];
    __shared__ __align__(16) float Bs[2][GBK][36];

    const int tid = threadIdx.x;
    const int tm  = tid >> 3;
    const int tn  = tid & 7;

    const int lrow = tid >> 1;
    const int lc   = (tid & 1) * 8;

    const float* Aptr = A + (size_t)(m0 + lrow) * K   + lc;
    const float* Bptr = B + (size_t)(n0 + lrow) * ldb + lc;

    ULL acc[4][2];
#pragma unroll
    for (int i = 0; i < 4; i++) { acc[i][0] = 0ull; acc[i][1] = 0ull; }

    const int KC = K / GBK;

    float4 pa0 = *(const float4*)(Aptr);
    float4 pa1 = *(const float4*)(Aptr + 4);
    float4 pb0 = *(const float4*)(Bptr);
    float4 pb1 = *(const float4*)(Bptr + 4);

    {
        As[0][lc    ][lrow] = pa0.x; As[0][lc + 1][lrow] = pa0.y;
        As[0][lc + 2][lrow] = pa0.z; As[0][lc + 3][lrow] = pa0.w;
        As[0][lc + 4][lrow] = pa1.x; As[0][lc + 5][lrow] = pa1.y;
        As[0][lc + 6][lrow] = pa1.z; As[0][lc + 7][lrow] = pa1.w;
        Bs[0][lc    ][lrow] = pb0.x; Bs[0][lc + 1][lrow] = pb0.y;
        Bs[0][lc + 2][lrow] = pb0.z; Bs[0][lc + 3][lrow] = pb0.w;
        Bs[0][lc + 4][lrow] = pb1.x; Bs[0][lc + 5][lrow] = pb1.y;
        Bs[0][lc + 6][lrow] = pb1.z; Bs[0][lc + 7][lrow] = pb1.w;
    }
    __syncthreads();

    for (int kc = 0; kc < KC; kc++) {
        const int cur = kc & 1;
        if (kc + 1 < KC) {
            pa0 = *(const float4*)(Aptr + (kc + 1) * GBK);
            pa1 = *(const float4*)(Aptr + (kc + 1) * GBK + 4);
            pb0 = *(const float4*)(Bptr + (kc + 1) * GBK);
            pb1 = *(const float4*)(Bptr + (kc + 1) * GBK + 4);
        }
#pragma unroll
        for (int k = 0; k < GBK; k++) {
            float4     av = *(const float4*)    &As[cur][k][tm * 4];
            ulonglong2 bv = *(const ulonglong2*)&Bs[cur][k][tn * 4];
            acc[0][0] = fma2(pack2(av.x, av.x), bv.x, acc[0][0]);
            acc[0][1] = fma2(pack2(av.x, av.x), bv.y, acc[0][1]);
            acc[1][0] = fma2(pack2(av.y, av.y), bv.x, acc[1][0]);
            acc[1][1] = fma2(pack2(av.y, av.y), bv.y, acc[1][1]);
            acc[2][0] = fma2(pack2(av.z, av.z), bv.x, acc[2][0]);
            acc[2][1] = fma2(pack2(av.z, av.z), bv.y, acc[2][1]);
            acc[3][0] = fma2(pack2(av.w, av.w), bv.x, acc[3][0]);
            acc[3][1] = fma2(pack2(av.w, av.w), bv.y, acc[3][1]);
        }
        if (kc + 1 < KC) {
            const int nxt = cur ^ 1;
            As[nxt][lc    ][lrow] = pa0.x; As[nxt][lc + 1][lrow] = pa0.y;
            As[nxt][lc + 2][lrow] = pa0.z; As[nxt][lc + 3][lrow] = pa0.w;
            As[nxt][lc + 4][lrow] = pa1.x; As[nxt][lc + 5][lrow] = pa1.y;
            As[nxt][lc + 6][lrow] = pa1.z; As[nxt][lc + 7][lrow] = pa1.w;
            Bs[nxt][lc    ][lrow] = pb0.x; Bs[nxt][lc + 1][lrow] = pb0.y;
            Bs[nxt][lc + 2][lrow] = pb0.z; Bs[nxt][lc + 3][lrow] = pb0.w;
            Bs[nxt][lc + 4][lrow] = pb1.x; Bs[nxt][lc + 5][lrow] = pb1.y;
            Bs[nxt][lc + 6][lrow] = pb1.z; Bs[nxt][lc + 7][lrow] = pb1.w;
            __syncthreads();
        }
    }

    float b0 = 0.f, b1 = 0.f, b2 = 0.f, b3 = 0.f;
    if (bias) {
        b0 = bias[n0 + tn * 4];     b1 = bias[n0 + tn * 4 + 1];
        b2 = bias[n0 + tn * 4 + 2]; b3 = bias[n0 + tn * 4 + 3];
    }
#pragma unroll
    for (int i = 0; i < 4; i++) {
        float2 c01 = unpack2(acc[i][0]);
        float2 c23 = unpack2(acc[i][1]);
        float4 o = make_float4(c01.x + b0, c01.y + b1, c23.x + b2, c23.y + b3);
        if (relu) {
            o.x = fmaxf(o.x, 0.f); o.y = fmaxf(o.y, 0.f);
            o.z = fmaxf(o.z, 0.f); o.w = fmaxf(o.w, 0.f);
        }
        *(float4*)(C + (size_t)(m0 + tm * 4 + i) * N + n0 + tn * 4) = o;
    }
}

// ---------------------------------------------------------------------------
// pair_mma: out[b,i,n,j] = sum_h relu(s2[b,i,h] + t2[b,j,h]) * fc3[n,h]
// via tf32 mma.sync.m16n8k8; the pair tensor is built per-fragment in
// registers (fused add+relu+cvt.rna.tf32) and never materialized.
//
// CTA: b fixed, j-tile 32, i-group 8. 4 warps: w&1 -> j half (16 rows),
// w>>1 -> i half (4 rows). Per k-step the t- and W-fragments are loaded
// once and reused across the 4-i block (key change vs R3).
// N padded 25->32 with zero-filled fc3. ld=268 keeps every fragment LDS
// on 32 distinct banks. smem 77 KB -> 2 CTAs/SM.
// ---------------------------------------------------------------------------
#define PLD 268
#define SM_T2  0
#define SM_W   (32 * PLD)
#define SM_S   (64 * PLD)
#define PAIR_SMEM (72 * PLD * 4)

__global__ __launch_bounds__(128) void pair_mma(
    const float* __restrict__ s2, const float* __restrict__ t2,
    const float* __restrict__ fc3, float* __restrict__ out)
{
    extern __shared__ float sm[];
    const int jt = blockIdx.x;   // 0..7   (j tile of 32)
    const int ig = blockIdx.y;   // 0..31  (i group of 8)
    const int b  = blockIdx.z;   // 0..3

    const int tid  = threadIdx.x;
    const int w    = tid >> 5;
    const int lane = tid & 31;
    const int g    = lane >> 2;   // 0..7
    const int tg   = lane & 3;    // 0..3
    const int wj   = w & 1;       // j half
    const int wi   = w >> 1;      // i half

    // ---- stage tiles ----
    // t2 tile: 32 rows x 256 h
    {
        const float* t2g = t2 + (size_t)(b * 256 + jt * 32) * 256;
#pragma unroll
        for (int r = 0; r < 16; r++) {
            int q   = tid + r * 128;        // 0..2047
            int row = q >> 6;               // 0..31
            int c4  = (q & 63) * 4;         // 0..252
            float4 v = *(const float4*)(t2g + row * 256 + c4);
            *(float4*)&sm[SM_T2 + row * PLD + c4] = v;
        }
    }
    // fc3 -> tf32 bits, zero-padded to n=32
    for (int q = tid; q < 32 * 256; q += 128) {
        int n = q >> 8;
        int h = q & 255;
        float v = (n < 25) ? fc3[n * 256 + h] : 0.f;
        sm[SM_W + n * PLD + h] = __uint_as_float(tf32r(v));
    }
    // s2 rows for this i-group (8 rows)
    {
        const float* s2g = s2 + (size_t)(b * 256 + ig * 8) * 256;
        for (int q = tid; q < 8 * 256; q += 128) {
            int row = q >> 8;
            int h = q & 255;
            sm[SM_S + row * PLD + h] = s2g[row * 256 + h];
        }
    }
    __syncthreads();

    const float* tA = sm + SM_T2 + (wj * 16 + g) * PLD + tg;  // t rows (j)
    const float* tW = sm + SM_W  + g * PLD + tg;              // fc3 rows (n)
    const float* tS = sm + SM_S  + wi * 4 * PLD + tg;         // s2 rows (i)

    float acc[4][4][4];   // [i][nt][c]
#pragma unroll
    for (int i = 0; i < 4; i++)
#pragma unroll
        for (int nt = 0; nt < 4; nt++)
#pragma unroll
            for (int c = 0; c < 4; c++) acc[i][nt][c] = 0.f;

#pragma unroll 2
    for (int ks = 0; ks < 32; ks++) {
        const int k0 = ks * 8;
        // t fragments: shared across the 4-i block
        float t0 = tA[k0];
        float t1 = tA[k0 + 8 * PLD];
        float t2v = tA[k0 + 4];
        float t3 = tA[k0 + 4 + 8 * PLD];
        // W fragments: shared across the 4-i block
        U32 wb0[4], wb1[4];
#pragma unroll
        for (int nt = 0; nt < 4; nt++) {
            wb0[nt] = __float_as_uint(tW[nt * 8 * PLD + k0]);
            wb1[nt] = __float_as_uint(tW[nt * 8 * PLD + k0 + 4]);
        }
#pragma unroll
        for (int i = 0; i < 4; i++) {
            float s0 = tS[i * PLD + k0];
            float s1 = tS[i * PLD + k0 + 4];
            U32 a0 = tf32r(fmaxf(t0  + s0, 0.f));
            U32 a1 = tf32r(fmaxf(t1  + s0, 0.f));
            U32 a2 = tf32r(fmaxf(t2v + s1, 0.f));
            U32 a3 = tf32r(fmaxf(t3  + s1, 0.f));
#pragma unroll
            for (int nt = 0; nt < 4; nt++) {
                asm volatile(
                    "mma.sync.aligned.m16n8k8.row.col.f32.tf32.tf32.f32 "
                    "{%0,%1,%2,%3}, {%4,%5,%6,%7}, {%8,%9}, {%0,%1,%2,%3};"
                    : "+f"(acc[i][nt][0]), "+f"(acc[i][nt][1]),
                      "+f"(acc[i][nt][2]), "+f"(acc[i][nt][3])
                    : "r"(a0), "r"(a1), "r"(a2), "r"(a3),
                      "r"(wb0[nt]), "r"(wb1[nt]));
            }
        }
    }

    // store: D rows = j, cols = n.  c0:(j=g,n0) c1:(g,n0+1) c2:(g+8,n0) c3:(g+8,n0+1)
    const int jg = jt * 32 + wj * 16 + g;
#pragma unroll
    for (int i = 0; i < 4; i++) {
        const int ii = ig * 8 + wi * 4 + i;
        float* obase = out + ((size_t)(b * 256 + ii) * 25) * 256 + jg;
#pragma unroll
        for (int nt = 0; nt < 4; nt++) {
            int n0 = nt * 8 + tg * 2;
            if (n0 < 25) {
                obase[(size_t)n0 * 256]     = acc[i][nt][0];
                obase[(size_t)n0 * 256 + 8] = acc[i][nt][2];
            }
            if (n0 + 1 < 25) {
                obase[(size_t)(n0 + 1) * 256]     = acc[i][nt][1];
                obase[(size_t)(n0 + 1) * 256 + 8] = acc[i][nt][3];
            }
        }
    }
}

// ---------------------------------------------------------------------------
// Inputs (metadata order):
// 0 input_tensor [4,256,768]  1 s_fc_w [256,768]  2 s_fc_b [256]
// 3 t_fc_w [256,768]          4 t_fc_b [256]      5 fc2_w [256,512]
// 6 fc2_b [256]               7 fc3_w [25,256]
// Output: float32 [4,256,25,256]
// ---------------------------------------------------------------------------
extern "C" void kernel_launch(void* const* d_in, const int* in_sizes, int n_in,
                              void* d_out, int out_size)
{
    const float* X  = (const float*)d_in[0];
    const float* sw = (const float*)d_in[1];
    const float* sb = (const float*)d_in[2];
    const float* tw = (const float*)d_in[3];
    const float* tb = (const float*)d_in[4];
    const float* w2 = (const float*)d_in[5];
    const float* b2 = (const float*)d_in[6];
    const float* w3 = (const float*)d_in[7];
    float* out = (float*)d_out;

    float *gs, *gt, *gs2, *gt2;
    cudaGetSymbolAddress((void**)&gs,  g_s);
    cudaGetSymbolAddress((void**)&gt,  g_t);
    cudaGetSymbolAddress((void**)&gs2, g_s2);
    cudaGetSymbolAddress((void**)&gt2, g_t2);

    cudaFuncSetAttribute(pair_mma, cudaFuncAttributeMaxDynamicSharedMemorySize,
                         PAIR_SMEM);

    dim3 blk(64);
    dim3 g1(256 / 32, 1024 / 32, 2);   // 512 CTAs
    // s = relu(X @ s_fc_w^T + s_fc_b), t = relu(X @ t_fc_w^T + t_fc_b)
    gemm_s<<<g1, blk>>>(X, X, sw, tw, sb, tb, gs, gt, 768, 768, 256, 1);
    // s2 = s @ w_s^T ; t2 = t @ w_t^T + fc2_b
    gemm_s<<<g1, blk>>>(gs, gt, w2, w2 + 256, nullptr, b2, gs2, gt2, 256, 512, 256, 0);

    dim3 g3(8, 32, 4);                 // 1024 CTAs
    pair_mma<<<g3, dim3(128), PAIR_SMEM>>>(gs2, gt2, w3, out);
}

// round 5
// speedup vs baseline: 2.0673x; 1.5277x over previous
#include <cuda_runtime.h>

typedef unsigned int U32;

__device__ __forceinline__ U32 tf32r(float x) {
    U32 r;
    asm("cvt.rna.tf32.f32 %0, %1;" : "=r"(r) : "f"(x));
    return r;
}
__device__ __forceinline__ void cp16(U32 dst, const void* src) {
    asm volatile("cp.async.ca.shared.global [%0], [%1], 16;" :: "r"(dst), "l"(src));
}
__device__ __forceinline__ void cp_commit() {
    asm volatile("cp.async.commit_group;");
}
__device__ __forceinline__ void cp_wait1() {
    asm volatile("cp.async.wait_group 1;");
}
__device__ __forceinline__ void cp_wait0() {
    asm volatile("cp.async.wait_group 0;");
}
__device__ __forceinline__ void mma_tf32(
    float& c0, float& c1, float& c2, float& c3,
    U32 a0, U32 a1, U32 a2, U32 a3, U32 b0, U32 b1)
{
    asm volatile(
        "mma.sync.aligned.m16n8k8.row.col.f32.tf32.tf32.f32 "
        "{%0,%1,%2,%3}, {%4,%5,%6,%7}, {%8,%9}, {%0,%1,%2,%3};"
        : "+f"(c0), "+f"(c1), "+f"(c2), "+f"(c3)
        : "r"(a0), "r"(a1), "r"(a2), "r"(a3), "r"(b0), "r"(b1));
}

// Scratch (cudaMalloc forbidden; __device__ globals allowed)
__device__ float g_s [1024 * 256];
__device__ float g_t [1024 * 256];
__device__ float g_s2[1024 * 256];
__device__ float g_t2[1024 * 256];

// ---------------------------------------------------------------------------
// gemm_tc: C[m][n] = act( sum_k A[m*K+k] * B[n*ldb+k] + bias[n] )
// Split-tf32 tensor-core GEMM: a = a_hi + a_lo (tf32 pair), accumulating
// hi*hi + hi*lo + lo*hi  ->  ~fp32 accuracy (err ~2^-22).
// CTA tile 32m x 64n, 64 threads (2 warps: warp w = m-half of 16 rows,
// covering all 64 n as 8 n-tiles). K-chunk 32, cp.async double buffer.
// blockIdx.z selects the {A,B,bias,C} set (s/t branches concurrent).
// ---------------------------------------------------------------------------
__global__ __launch_bounds__(64) void gemm_tc(
    const float* __restrict__ A0, const float* __restrict__ A1,
    const float* __restrict__ B0, const float* __restrict__ B1,
    const float* __restrict__ bias0, const float* __restrict__ bias1,
    float* __restrict__ C0, float* __restrict__ C1,
    int K, int ldb, int N, int relu)
{
    const float* A    = blockIdx.z ? A1 : A0;
    const float* B    = blockIdx.z ? B1 : B0;
    const float* bias = blockIdx.z ? bias1 : bias0;
    float*       C    = blockIdx.z ? C1 : C0;

    const int m0 = blockIdx.y * 32;
    const int n0 = blockIdx.x * 64;

    __shared__ __align__(16) float As[2][32][36];
    __shared__ __align__(16) float Bs[2][64][36];

    const int tid  = threadIdx.x;
    const int w    = tid >> 5;
    const int lane = tid & 31;
    const int g    = lane >> 2;   // 0..7
    const int tg   = lane & 3;    // 0..3

    const U32 asB = (U32)__cvta_generic_to_shared(&As[0][0][0]);
    const U32 bsB = (U32)__cvta_generic_to_shared(&Bs[0][0][0]);
    const U32 bufA = 32 * 36 * 4;
    const U32 bufB = 64 * 36 * 4;

    // loader coords (64 threads): idx>>3 = row, (idx&7)*4 = k-quad
    const int arow = tid >> 3;          // A rows handled with stride 8
    const int kq   = (tid & 7) * 4;

    const int KC = K / 32;

    // stage chunk 0
    {
#pragma unroll
        for (int r = 0; r < 4; r++) {
            int row = arow + r * 8;
            cp16(asB + (row * 36 + kq) * 4, A + (size_t)(m0 + row) * K + kq);
        }
#pragma unroll
        for (int r = 0; r < 8; r++) {
            int row = arow + r * 8;
            cp16(bsB + (row * 36 + kq) * 4, B + (size_t)(n0 + row) * ldb + kq);
        }
        cp_commit();
    }

    float acc[8][4];
#pragma unroll
    for (int nt = 0; nt < 8; nt++)
#pragma unroll
        for (int c = 0; c < 4; c++) acc[nt][c] = 0.f;

    const int r0 = w * 16 + g;

    for (int kc = 0; kc < KC; kc++) {
        const int cur = kc & 1;
        if (kc + 1 < KC) {
            const int nxt = cur ^ 1;
            const int koff = (kc + 1) * 32;
#pragma unroll
            for (int r = 0; r < 4; r++) {
                int row = arow + r * 8;
                cp16(asB + nxt * bufA + (row * 36 + kq) * 4,
                     A + (size_t)(m0 + row) * K + koff + kq);
            }
#pragma unroll
            for (int r = 0; r < 8; r++) {
                int row = arow + r * 8;
                cp16(bsB + nxt * bufB + (row * 36 + kq) * 4,
                     B + (size_t)(n0 + row) * ldb + koff + kq);
            }
            cp_commit();
            cp_wait1();
        } else {
            cp_wait0();
        }
        __syncthreads();

#pragma unroll
        for (int ks = 0; ks < 4; ks++) {
            const int k0 = ks * 8;
            float a00 = As[cur][r0    ][k0 + tg];
            float a10 = As[cur][r0 + 8][k0 + tg];
            float a01 = As[cur][r0    ][k0 + tg + 4];
            float a11 = As[cur][r0 + 8][k0 + tg + 4];
            U32 ah0 = tf32r(a00), ah1 = tf32r(a10), ah2 = tf32r(a01), ah3 = tf32r(a11);
            U32 al0 = tf32r(a00 - __uint_as_float(ah0));
            U32 al1 = tf32r(a10 - __uint_as_float(ah1));
            U32 al2 = tf32r(a01 - __uint_as_float(ah2));
            U32 al3 = tf32r(a11 - __uint_as_float(ah3));
#pragma unroll
            for (int nt = 0; nt < 8; nt++) {
                float b0f = Bs[cur][nt * 8 + g][k0 + tg];
                float b1f = Bs[cur][nt * 8 + g][k0 + tg + 4];
                U32 bh0 = tf32r(b0f), bh1 = tf32r(b1f);
                U32 bl0 = tf32r(b0f - __uint_as_float(bh0));
                U32 bl1 = tf32r(b1f - __uint_as_float(bh1));
                mma_tf32(acc[nt][0], acc[nt][1], acc[nt][2], acc[nt][3],
                         ah0, ah1, ah2, ah3, bh0, bh1);
                mma_tf32(acc[nt][0], acc[nt][1], acc[nt][2], acc[nt][3],
                         ah0, ah1, ah2, ah3, bl0, bl1);
                mma_tf32(acc[nt][0], acc[nt][1], acc[nt][2], acc[nt][3],
                         al0, al1, al2, al3, bh0, bh1);
            }
        }
        __syncthreads();
    }

    // epilogue: D rows = m (c0:(g,2tg) c1:(g,2tg+1) c2:(g+8,2tg) c3:(g+8,2tg+1))
#pragma unroll
    for (int nt = 0; nt < 8; nt++) {
        const int col = n0 + nt * 8 + tg * 2;
        float b0 = 0.f, b1 = 0.f;
        if (bias) { b0 = bias[col]; b1 = bias[col + 1]; }
        float2 v0 = make_float2(acc[nt][0] + b0, acc[nt][1] + b1);
        float2 v1 = make_float2(acc[nt][2] + b0, acc[nt][3] + b1);
        if (relu) {
            v0.x = fmaxf(v0.x, 0.f); v0.y = fmaxf(v0.y, 0.f);
            v1.x = fmaxf(v1.x, 0.f); v1.y = fmaxf(v1.y, 0.f);
        }
        *(float2*)(C + (size_t)(m0 + r0)     * N + col) = v0;
        *(float2*)(C + (size_t)(m0 + r0 + 8) * N + col) = v1;
    }
}

// ---------------------------------------------------------------------------
// pair_mma: out[b,i,n,j] = sum_h relu(s2[b,i,h] + t2[b,j,h]) * fc3[n,h]
// via tf32 mma.sync.m16n8k8; pair fragments built in registers (fused
// add+relu+cvt), never materialized.
// 256 threads (8 warps): wj = w&1 (j half of 16), wi = w>>2? no: w>>1 (0..3)
// -> i quarter (4 rows of the 16-row i-group). 2 CTAs/SM -> 4 warps/SMSP.
// ---------------------------------------------------------------------------
#define PLD 268
#define SM_T2  0
#define SM_W   (32 * PLD)
#define SM_S   (64 * PLD)
#define PAIR_SMEM (80 * PLD * 4)

__global__ __launch_bounds__(256, 2) void pair_mma(
    const float* __restrict__ s2, const float* __restrict__ t2,
    const float* __restrict__ fc3, float* __restrict__ out)
{
    extern __shared__ float sm[];
    const int jt = blockIdx.x;   // 0..7   (j tile of 32)
    const int ig = blockIdx.y;   // 0..15  (i group of 16)
    const int b  = blockIdx.z;   // 0..3

    const int tid  = threadIdx.x;
    const int w    = tid >> 5;    // 0..7
    const int lane = tid & 31;
    const int g    = lane >> 2;   // 0..7
    const int tg   = lane & 3;    // 0..3
    const int wj   = w & 1;       // j half
    const int wi   = w >> 1;      // i quarter (0..3)

    // ---- stage tiles ----
    {   // t2 tile: 32 rows x 256 h
        const float* t2g = t2 + (size_t)(b * 256 + jt * 32) * 256;
#pragma unroll
        for (int r = 0; r < 8; r++) {
            int q   = tid + r * 256;        // 0..2047
            int row = q >> 6;               // 0..31
            int c4  = (q & 63) * 4;
            float4 v = *(const float4*)(t2g + row * 256 + c4);
            *(float4*)&sm[SM_T2 + row * PLD + c4] = v;
        }
    }
    // fc3 -> tf32 bits, zero-padded to n=32
    for (int q = tid; q < 32 * 256; q += 256) {
        int n = q >> 8;
        int h = q & 255;
        float v = (n < 25) ? fc3[n * 256 + h] : 0.f;
        sm[SM_W + n * PLD + h] = __uint_as_float(tf32r(v));
    }
    {   // s2 rows for this i-group (16 rows)
        const float* s2g = s2 + (size_t)(b * 256 + ig * 16) * 256;
        for (int q = tid; q < 16 * 256; q += 256) {
            int row = q >> 8;
            int h = q & 255;
            sm[SM_S + row * PLD + h] = s2g[row * 256 + h];
        }
    }
    __syncthreads();

    const float* tA = sm + SM_T2 + (wj * 16 + g) * PLD + tg;  // t rows (j)
    const float* tW = sm + SM_W  + g * PLD + tg;              // fc3 rows (n)
    const float* tS = sm + SM_S  + wi * 4 * PLD + tg;         // s2 rows (i)

    float acc[4][4][4];   // [i][nt][c]
#pragma unroll
    for (int i = 0; i < 4; i++)
#pragma unroll
        for (int nt = 0; nt < 4; nt++)
#pragma unroll
            for (int c = 0; c < 4; c++) acc[i][nt][c] = 0.f;

#pragma unroll 2
    for (int ks = 0; ks < 32; ks++) {
        const int k0 = ks * 8;
        // t fragments: shared across the 4-i block
        float t0  = tA[k0];
        float t1  = tA[k0 + 8 * PLD];
        float t2v = tA[k0 + 4];
        float t3  = tA[k0 + 4 + 8 * PLD];
        // W fragments: shared across the 4-i block
        U32 wb0[4], wb1[4];
#pragma unroll
        for (int nt = 0; nt < 4; nt++) {
            wb0[nt] = __float_as_uint(tW[nt * 8 * PLD + k0]);
            wb1[nt] = __float_as_uint(tW[nt * 8 * PLD + k0 + 4]);
        }
#pragma unroll
        for (int i = 0; i < 4; i++) {
            float s0 = tS[i * PLD + k0];
            float s1 = tS[i * PLD + k0 + 4];
            U32 a0 = tf32r(fmaxf(t0  + s0, 0.f));
            U32 a1 = tf32r(fmaxf(t1  + s0, 0.f));
            U32 a2 = tf32r(fmaxf(t2v + s1, 0.f));
            U32 a3 = tf32r(fmaxf(t3  + s1, 0.f));
#pragma unroll
            for (int nt = 0; nt < 4; nt++) {
                mma_tf32(acc[i][nt][0], acc[i][nt][1], acc[i][nt][2], acc[i][nt][3],
                         a0, a1, a2, a3, wb0[nt], wb1[nt]);
            }
        }
    }

    // store: D rows = j, cols = n
    const int jg = jt * 32 + wj * 16 + g;
#pragma unroll
    for (int i = 0; i < 4; i++) {
        const int ii = ig * 16 + wi * 4 + i;
        float* obase = out + ((size_t)(b * 256 + ii) * 25) * 256 + jg;
#pragma unroll
        for (int nt = 0; nt < 4; nt++) {
            int n0 = nt * 8 + tg * 2;
            if (n0 < 25) {
                obase[(size_t)n0 * 256]     = acc[i][nt][0];
                obase[(size_t)n0 * 256 + 8] = acc[i][nt][2];
            }
            if (n0 + 1 < 25) {
                obase[(size_t)(n0 + 1) * 256]     = acc[i][nt][1];
                obase[(size_t)(n0 + 1) * 256 + 8] = acc[i][nt][3];
            }
        }
    }
}

// ---------------------------------------------------------------------------
// Inputs (metadata order):
// 0 input_tensor [4,256,768]  1 s_fc_w [256,768]  2 s_fc_b [256]
// 3 t_fc_w [256,768]          4 t_fc_b [256]      5 fc2_w [256,512]
// 6 fc2_b [256]               7 fc3_w [25,256]
// Output: float32 [4,256,25,256]
// ---------------------------------------------------------------------------
extern "C" void kernel_launch(void* const* d_in, const int* in_sizes, int n_in,
                              void* d_out, int out_size)
{
    const float* X  = (const float*)d_in[0];
    const float* sw = (const float*)d_in[1];
    const float* sb = (const float*)d_in[2];
    const float* tw = (const float*)d_in[3];
    const float* tb = (const float*)d_in[4];
    const float* w2 = (const float*)d_in[5];
    const float* b2 = (const float*)d_in[6];
    const float* w3 = (const float*)d_in[7];
    float* out = (float*)d_out;

    float *gs, *gt, *gs2, *gt2;
    cudaGetSymbolAddress((void**)&gs,  g_s);
    cudaGetSymbolAddress((void**)&gt,  g_t);
    cudaGetSymbolAddress((void**)&gs2, g_s2);
    cudaGetSymbolAddress((void**)&gt2, g_t2);

    cudaFuncSetAttribute(pair_mma, cudaFuncAttributeMaxDynamicSharedMemorySize,
                         PAIR_SMEM);

    dim3 blk(64);
    dim3 g1(256 / 64, 1024 / 32, 2);   // 4 x 32 x 2 = 256 CTAs
    // s = relu(X @ s_fc_w^T + s_fc_b), t = relu(X @ t_fc_w^T + t_fc_b)
    gemm_tc<<<g1, blk>>>(X, X, sw, tw, sb, tb, gs, gt, 768, 768, 256, 1);
    // s2 = s @ w_s^T ; t2 = t @ w_t^T + fc2_b
    gemm_tc<<<g1, blk>>>(gs, gt, w2, w2 + 256, nullptr, b2, gs2, gt2, 256, 512, 256, 0);

    dim3 g3(8, 16, 4);                 // 512 CTAs, 256 threads
    pair_mma<<<g3, dim3(256), PAIR_SMEM>>>(gs2, gt2, w3, out);
}